// round 1
// baseline (speedup 1.0000x reference)
#include <cuda_runtime.h>

#define BB 16
#define HH 512
#define WW 512
#define HW (HH*WW)
#define NN (BB*HW)

// scratch (device globals; no allocation allowed)
__device__ unsigned char g_A[NN];
__device__ unsigned char g_Bm[NN];
__device__ int g_L[NN];
__device__ int g_sz[NN];
__device__ int g_nc[BB];

// ---------------- elementwise helpers ----------------

__global__ void k_thresh(const float* __restrict__ in) {
    int i = blockIdx.x * blockDim.x + threadIdx.x;
    if (i < NN) g_A[i] = (in[i] > 0.0f) ? 1 : 0;
}

__global__ void k_init() {
    int i = blockIdx.x * blockDim.x + threadIdx.x;
    if (i < NN) { g_L[i] = i; g_sz[i] = 0; }
    if (i < BB) g_nc[i] = 0;
}

// ---------------- union-find CCL ----------------

__device__ __forceinline__ int findroot(int* L, int i) {
    volatile int* V = L;
    int p = V[i];
    while (p != i) { i = p; p = V[i]; }
    return i;
}

__device__ void unite(int* L, int a, int b) {
    while (true) {
        a = findroot(L, a);
        b = findroot(L, b);
        if (a == b) return;
        if (a > b) { int t = a; a = b; b = t; }
        int old = atomicMin(&L[b], a);
        if (old == b) return;
        b = old;  // someone else re-rooted b; keep merging
    }
}

// 4-connectivity: union with left and up neighbors. inv=1 means label background.
__global__ void k_merge(const unsigned char* __restrict__ fg, int inv) {
    int i = blockIdx.x * blockDim.x + threadIdx.x;
    if (i >= NN) return;
    if (fg[i] == inv) return;                 // inactive pixel
    int x = i % WW;
    int yloc = (i % HW) / WW;
    if (x > 0   && fg[i - 1]  != inv) unite(g_L, i, i - 1);
    if (yloc > 0 && fg[i - WW] != inv) unite(g_L, i, i - WW);
}

__global__ void k_compress() {
    int i = blockIdx.x * blockDim.x + threadIdx.x;
    if (i < NN) g_L[i] = findroot(g_L, i);
}

__global__ void k_count(const unsigned char* __restrict__ fg, int inv) {
    int i = blockIdx.x * blockDim.x + threadIdx.x;
    if (i >= NN) return;
    if (fg[i] == inv) return;
    int r = g_L[i];
    atomicAdd(&g_sz[r], 1);
    if (r == i) atomicAdd(&g_nc[i / HW], 1);   // one root per component
}

// remove components smaller than min_size; guarded by ncomp>1 if use_guard
__global__ void k_filter_small(unsigned char* fg, int min_size, int use_guard) {
    int i = blockIdx.x * blockDim.x + threadIdx.x;
    if (i >= NN) return;
    if (!fg[i]) return;
    if (use_guard && g_nc[i / HW] <= 1) return;
    if (g_sz[g_L[i]] < min_size) fg[i] = 0;
}

// fill background components with size < thresh (CCL was run with inv=1)
__global__ void k_fill(unsigned char* fg, int thresh) {
    int i = blockIdx.x * blockDim.x + threadIdx.x;
    if (i >= NN) return;
    if (fg[i]) return;
    if (g_sz[g_L[i]] < thresh) fg[i] = 1;
}

// ---------------- morphology ----------------

// shared-tile erode/dilate by disk of radius R.
// erosion: out-of-bounds counts as fg (border_value=1); dilation: as bg.
template <int R, bool ER>
__global__ void k_morph(const unsigned char* __restrict__ in,
                        unsigned char* __restrict__ out) {
    constexpr int T = 32 + 2 * R;
    __shared__ unsigned char s[T * T];
    int b  = blockIdx.z;
    int bx = blockIdx.x * 32, by = blockIdx.y * 32;
    const unsigned char* img = in + b * HW;

    for (int t = threadIdx.y * 32 + threadIdx.x; t < T * T; t += 1024) {
        int ly = t / T, lx = t % T;
        int gy = by + ly - R, gx = bx + lx - R;
        unsigned char v = ER ? 1 : 0;
        if (gy >= 0 && gy < HH && gx >= 0 && gx < WW) v = img[gy * WW + gx];
        s[t] = v;
    }
    __syncthreads();

    int acc = ER ? 1 : 0;
#pragma unroll
    for (int dy = -R; dy <= R; dy++) {
#pragma unroll
        for (int dx = -R; dx <= R; dx++) {
            if (dx * dx + dy * dy <= R * R) {
                int v = s[(threadIdx.y + R + dy) * T + (threadIdx.x + R + dx)];
                if (ER) acc &= v; else acc |= v;
            }
        }
    }
    out[b * HW + (by + threadIdx.y) * WW + (bx + threadIdx.x)] = (unsigned char)acc;
}

// final dilate by disk(1) (plus shape), write float
__global__ void k_dilate1_f(const unsigned char* __restrict__ in,
                            float* __restrict__ out) {
    int i = blockIdx.x * blockDim.x + threadIdx.x;
    if (i >= NN) return;
    int x = i % WW;
    int yloc = (i % HW) / WW;
    unsigned char v = in[i];
    if (x > 0)        v |= in[i - 1];
    if (x < WW - 1)   v |= in[i + 1];
    if (yloc > 0)     v |= in[i - WW];
    if (yloc < HH - 1) v |= in[i + WW];
    out[i] = (float)v;
}

// ---------------- launch ----------------

extern "C" void kernel_launch(void* const* d_in, const int* in_sizes, int n_in,
                              void* d_out, int out_size) {
    (void)in_sizes; (void)n_in; (void)out_size;
    const float* in = (const float*)d_in[0];
    float* out = (float*)d_out;

    unsigned char *A, *Bm;
    cudaGetSymbolAddress((void**)&A,  g_A);
    cudaGetSymbolAddress((void**)&Bm, g_Bm);

    const int nb = (NN + 255) / 256;
    dim3 mg(WW / 32, HH / 32, BB), mb(32, 32);

    auto ccl = [&](unsigned char* fg, int inv) {
        k_init<<<nb, 256>>>();
        k_merge<<<nb, 256>>>(fg, inv);
        k_compress<<<nb, 256>>>();
        k_count<<<nb, 256>>>(fg, inv);
    };

    // fg = input > 0
    k_thresh<<<nb, 256>>>(in);

    // remove_small_objects(fg, 2000, guarded)
    ccl(A, 0);
    k_filter_small<<<nb, 256>>>(A, 2000, 1);

    // fill holes: ~remove_small_objects(~fg, 301)
    ccl(A, 1);
    k_fill<<<nb, 256>>>(A, 301);

    // erode disk(2), then opening with disk(5)
    k_morph<2, true ><<<mg, mb>>>(A,  Bm);
    k_morph<5, true ><<<mg, mb>>>(Bm, A);
    k_morph<5, false><<<mg, mb>>>(A,  Bm);

    // remove_small_objects(fg, 2000, guarded)
    ccl(Bm, 0);
    k_filter_small<<<nb, 256>>>(Bm, 2000, 1);

    // dilate disk(1) -> float out
    k_dilate1_f<<<nb, 256>>>(Bm, out);
}

// round 5
// speedup vs baseline: 11.3843x; 11.3843x over previous
#include <cuda_runtime.h>

#define BB 16
#define HH 512
#define WW 512
#define HW (HH*WW)
#define NN (BB*HW)
#define WPR 16                 // words per row
#define WPI (HH*WPR)           // words per image = 8192
#define TOT (BB*WPI)           // total words = 131072

// bit j of word (b,y,w) = pixel x = w*32 + j ; pixel index = 32*wordIdx + j

__device__ unsigned g_F[TOT];
__device__ unsigned g_G[TOT];
__device__ int g_L[NN];
__device__ int g_sz[NN];
__device__ int g_nc[BB];

// ---------------- pack ----------------
__global__ void k_pack(const float* __restrict__ in) {
    int i = blockIdx.x * blockDim.x + threadIdx.x;
    if (i >= NN) return;
    unsigned b = __ballot_sync(0xffffffffu, in[i] > 0.0f);
    if ((i & 31) == 0) g_F[i >> 5] = b;
}

// ---------------- zero scratch ----------------
__global__ void k_zero() {
    int i = blockIdx.x * blockDim.x + threadIdx.x;
    if (i < NN / 4) ((int4*)g_sz)[i] = make_int4(0, 0, 0, 0);
    if (i < BB) g_nc[i] = 0;
}

// ---------------- union-find ----------------

// READ-ONLY root chase: never writes, safe under any concurrency.
__device__ __forceinline__ int findroot_ro(int i) {
    volatile int* V = g_L;
    int p = V[i];
    while (p != i) { i = p; p = V[i]; }
    return i;
}

__device__ void unite(int a, int b) {
    while (true) {
        a = findroot_ro(a);
        b = findroot_ro(b);
        if (a == b) return;
        if (a > b) { int t = a; a = b; b = t; }
        int old = atomicMin(&g_L[b], a);
        if (old == b) return;
        b = old;
    }
}

// run extraction helper: from mask m at bit j, length e of consecutive 1s
__device__ __forceinline__ int runlen(unsigned m, int j) {
    unsigned nt = ~(m >> j);
    return nt ? (__ffs(nt) - 1) : (32 - j);
}
__device__ __forceinline__ unsigned runmask(int j, int e) {
    return (e >= 32) ? 0xffffffffu : (((1u << e) - 1u) << j);
}

// ---------------- CCL kernels (INV: label the zero bits) ----------------
template<bool INV>
__global__ void k_cinit(const unsigned* __restrict__ F) {
    int t = blockIdx.x * blockDim.x + threadIdx.x;
    if (t >= TOT) return;
    unsigned m = F[t]; if (INV) m = ~m;
    if (!m) return;
    int base = t * 32;
    while (m) {
        int j = __ffs(m) - 1;
        int e = runlen(m, j);
        int lab = base + j;
        for (int q = 0; q < e; q++) g_L[lab + q] = lab;
        m &= ~runmask(j, e);
    }
}

template<bool INV>
__global__ void k_merge(const unsigned* __restrict__ F) {
    int t = blockIdx.x * blockDim.x + threadIdx.x;
    if (t >= TOT) return;
    int w = t & 15, y = (t >> 4) & 511;
    unsigned cur = F[t]; if (INV) cur = ~cur;
    if (!cur) return;
    int base = t * 32;
    if (w > 0 && (cur & 1u)) {
        unsigned left = F[t - 1]; if (INV) left = ~left;
        if (left >> 31) unite(base, base - 1);
    }
    if (y > 0) {
        unsigned up = F[t - WPR]; if (INV) up = ~up;
        unsigned ov = cur & up;
        unsigned starts = ov & ~(ov << 1);
        while (starts) {
            int j = __ffs(starts) - 1;
            starts &= starts - 1;
            unite(base + j, base + j - WW);
        }
    }
}

// Count sizes. Compression here is SINGLE-WRITER: only the thread owning word t
// writes g_L at run starts inside word t, and it writes the final root. No
// other thread writes g_L at all in this kernel (root chase is read-only).
template<bool INV>
__global__ void k_count(const unsigned* __restrict__ F) {
    int t = blockIdx.x * blockDim.x + threadIdx.x;
    if (t >= TOT) return;
    unsigned m = F[t]; if (INV) m = ~m;
    if (!m) return;
    int base = t * 32, b = t >> 13;
    while (m) {
        int j = __ffs(m) - 1;
        int e = runlen(m, j);
        int i = base + j;
        int r = findroot_ro(i);
        g_L[i] = r;                      // single-writer compression
        atomicAdd(&g_sz[r], e);          // aggregated per run
        if (r == i) atomicAdd(&g_nc[b], 1);
        m &= ~runmask(j, e);
    }
}

// resolve root at a run start (immediate when compression held; chase as insurance)
__device__ __forceinline__ int root_at(int i) {
    int r = g_L[i];
    while (g_L[r] != r) r = g_L[r];
    return r;
}

__global__ void k_filter(unsigned* F, int min_size, int use_guard) {
    int t = blockIdx.x * blockDim.x + threadIdx.x;
    if (t >= TOT) return;
    unsigned m = F[t];
    if (!m) return;
    int b = t >> 13;
    if (use_guard && g_nc[b] <= 1) return;
    int base = t * 32;
    unsigned keep = m, mm = m;
    while (mm) {
        int j = __ffs(mm) - 1;
        int e = runlen(mm, j);
        int r = root_at(base + j);
        if (g_sz[r] < min_size) keep &= ~runmask(j, e);
        mm &= ~runmask(j, e);
    }
    if (keep != m) F[t] = keep;
}

__global__ void k_fill(unsigned* F, int thresh) {
    int t = blockIdx.x * blockDim.x + threadIdx.x;
    if (t >= TOT) return;
    unsigned m = ~F[t];                  // background bits
    if (!m) return;
    int base = t * 32;
    unsigned add = 0, mm = m;
    while (mm) {
        int j = __ffs(mm) - 1;
        int e = runlen(mm, j);
        int r = root_at(base + j);
        if (g_sz[r] < thresh) add |= runmask(j, e);
        mm &= ~runmask(j, e);
    }
    if (add) F[t] |= add;
}

// ---------------- morphology on bitpacked ----------------
__host__ __device__ constexpr int hwidth(int R, int dy) {
    int w = 0;
    while ((w + 1) * (w + 1) + dy * dy <= R * R) ++w;
    return w;
}

template<int R, bool ER>
__global__ void k_morph(const unsigned* __restrict__ in, unsigned* __restrict__ out) {
    int t = blockIdx.x * blockDim.x + threadIdx.x;
    if (t >= TOT) return;
    int w = t & 15, y = (t >> 4) & 511, b = t >> 13;
    const unsigned* img = in + b * WPI;
    const unsigned border = ER ? 0xffffffffu : 0u;
    unsigned acc = border;
#pragma unroll
    for (int dy = -R; dy <= R; dy++) {
        int yy = y + dy;
        unsigned c, l, r;
        if (yy < 0 || yy >= HH) { c = border; l = border; r = border; }
        else {
            c = img[yy * WPR + w];
            l = (w > 0)  ? img[yy * WPR + w - 1] : border;
            r = (w < 15) ? img[yy * WPR + w + 1] : border;
        }
        unsigned rowacc = c;
        const int wd = hwidth(R, dy);
#pragma unroll
        for (int s = 1; s <= wd; s++) {
            unsigned rs = __funnelshift_r(c, r, s);   // sample x+s
            unsigned ls = __funnelshift_l(l, c, s);   // sample x-s
            if (ER) rowacc &= rs & ls; else rowacc |= rs | ls;
        }
        if (ER) acc &= rowacc; else acc |= rowacc;
    }
    out[t] = acc;
}

// ---------------- final dilate(disk1) + unpack float ----------------
__global__ void k_out(const unsigned* __restrict__ in, float* __restrict__ out) {
    int g = blockIdx.x * blockDim.x + threadIdx.x;
    if (g >= NN) return;
    int lane = g & 31;
    int t = g >> 5;
    int w = t & 15, y = (t >> 4) & 511, b = t >> 13;
    const unsigned* img = in + b * WPI;
    unsigned c = img[y * WPR + w];
    unsigned l = (w > 0)   ? img[y * WPR + w - 1] : 0u;
    unsigned r = (w < 15)  ? img[y * WPR + w + 1] : 0u;
    unsigned u = (y > 0)   ? img[(y - 1) * WPR + w] : 0u;
    unsigned d = (y < 511) ? img[(y + 1) * WPR + w] : 0u;
    unsigned res = c | u | d | __funnelshift_r(c, r, 1) | __funnelshift_l(l, c, 1);
    out[b * HW + y * WW + w * 32 + lane] = (float)((res >> lane) & 1u);
}

// ---------------- launch ----------------
extern "C" void kernel_launch(void* const* d_in, const int* in_sizes, int n_in,
                              void* d_out, int out_size) {
    (void)in_sizes; (void)n_in; (void)out_size;
    const float* in = (const float*)d_in[0];
    float* out = (float*)d_out;

    unsigned *F, *G;
    cudaGetSymbolAddress((void**)&F, g_F);
    cudaGetSymbolAddress((void**)&G, g_G);

    const int TPB = 256;
    const int gw = (TOT + TPB - 1) / TPB;        // word-granular kernels
    const int gp = (NN + TPB - 1) / TPB;         // pixel-granular kernels
    const int gz = (NN / 4 + TPB - 1) / TPB;     // zero kernel

    // pack: fg = input > 0
    k_pack<<<gp, TPB>>>(in);

    // --- remove_small_objects(fg, 2000, guarded) ---
    k_zero<<<gz, TPB>>>();
    k_cinit<false><<<gw, TPB>>>(F);
    k_merge<false><<<gw, TPB>>>(F);
    k_count<false><<<gw, TPB>>>(F);
    k_filter<<<gw, TPB>>>(F, 2000, 1);

    // --- fill small holes: bg components < 301 px ---
    k_zero<<<gz, TPB>>>();
    k_cinit<true><<<gw, TPB>>>(F);
    k_merge<true><<<gw, TPB>>>(F);
    k_count<true><<<gw, TPB>>>(F);
    k_fill<<<gw, TPB>>>(F, 301);

    // --- erode disk(2), then opening disk(5) ---
    k_morph<2, true ><<<gw, TPB>>>(F, G);
    k_morph<5, true ><<<gw, TPB>>>(G, F);
    k_morph<5, false><<<gw, TPB>>>(F, G);

    // --- remove_small_objects(fg, 2000, guarded) on G ---
    k_zero<<<gz, TPB>>>();
    k_cinit<false><<<gw, TPB>>>(G);
    k_merge<false><<<gw, TPB>>>(G);
    k_count<false><<<gw, TPB>>>(G);
    k_filter<<<gw, TPB>>>(G, 2000, 1);

    // --- dilate disk(1) -> float out ---
    k_out<<<gp, TPB>>>(G, out);
}

// round 6
// speedup vs baseline: 16.0022x; 1.4056x over previous
#include <cuda_runtime.h>

#define BB 16
#define HH 512
#define WW 512
#define HW (HH*WW)
#define NN (BB*HW)
#define WPR 16                 // words per row
#define WPI (HH*WPR)           // words per image = 8192
#define TOT (BB*WPI)           // total words = 131072

// bit j of word (b,y,w) = pixel x = w*32 + j ; pixel index = 32*wordIdx + j

__device__ unsigned g_F[TOT];
__device__ unsigned g_G[TOT];
__device__ int g_L[NN];
__device__ int g_sz[NN];
__device__ int g_nc[BB];

// ---------------- pack ----------------
__global__ void k_pack(const float* __restrict__ in) {
    int i = blockIdx.x * blockDim.x + threadIdx.x;
    if (i >= NN) return;
    unsigned b = __ballot_sync(0xffffffffu, in[i] > 0.0f);
    if ((i & 31) == 0) g_F[i >> 5] = b;
}

// ---------------- bit helpers ----------------
__device__ __forceinline__ int runlen(unsigned m, int j) {
    unsigned nt = ~(m >> j);
    return nt ? (__ffs(nt) - 1) : (32 - j);
}
__device__ __forceinline__ unsigned runmask(int j, int e) {
    return (e >= 32) ? 0xffffffffu : (((1u << e) - 1u) << j);
}
// start bit of the in-word run of m containing set bit j
__device__ __forceinline__ int rstart(unsigned m, int j) {
    unsigned zeros = (~m) & (j ? ((1u << j) - 1u) : 0u);
    return zeros ? (32 - __clz(zeros)) : 0;
}

// ---------------- union-find ----------------
// Root chase with atomicCAS path-halving. Safe vs concurrent atomicMin:
// CAS(p -> gp) fails if anything changed; both writers only decrease values
// toward ancestors, so connectivity and min-monotonicity are preserved.
__device__ __forceinline__ int findroot_h(int i) {
    volatile int* V = g_L;
    int p;
    while ((p = V[i]) != i) {
        int gp = V[p];
        if (gp == p) return p;
        atomicCAS(&g_L[i], p, gp);   // halve (may fail; fine)
        i = gp;
    }
    return i;
}

__device__ void unite(int a, int b) {
    while (true) {
        a = findroot_h(a);
        b = findroot_h(b);
        if (a == b) return;
        if (a > b) { int t = a; a = b; b = t; }
        int old = atomicMin(&g_L[b], a);
        if (old == b) return;
        b = old;
    }
}

// ---------------- CCL kernels (INV: label the zero bits) ----------------
// init: labels + size slots only at in-word run starts (the only indices used)
template<bool INV>
__global__ void k_cinit(const unsigned* __restrict__ F) {
    int t = blockIdx.x * blockDim.x + threadIdx.x;
    if (t >= TOT) return;
    if (t < BB) g_nc[t] = 0;
    unsigned m = F[t]; if (INV) m = ~m;
    if (!m) return;
    int base = t * 32;
    while (m) {
        int j = __ffs(m) - 1;
        int e = runlen(m, j);
        g_L[base + j]  = base + j;
        g_sz[base + j] = 0;
        m &= ~runmask(j, e);
    }
}

template<bool INV>
__global__ void k_merge(const unsigned* __restrict__ F) {
    int t = blockIdx.x * blockDim.x + threadIdx.x;
    if (t >= TOT) return;
    int w = t & 15, y = (t >> 4) & 511;
    unsigned cur = F[t]; if (INV) cur = ~cur;
    if (!cur) return;
    int base = t * 32;
    // horizontal stitch across word boundary
    if (w > 0 && (cur & 1u)) {
        unsigned left = F[t - 1]; if (INV) left = ~left;
        if (left >> 31) unite(base, (t - 1) * 32 + rstart(left, 31));
    }
    // vertical: one union per overlap-segment start
    if (y > 0) {
        unsigned up = F[t - WPR]; if (INV) up = ~up;
        unsigned ov = cur & up;
        unsigned starts = ov & ~(ov << 1);
        while (starts) {
            int j = __ffs(starts) - 1;
            starts &= starts - 1;
            unite(base + rstart(cur, j), base - WW + rstart(up, j));
        }
    }
}

// count sizes; compression store is by the owner thread only (writes true root)
template<bool INV>
__global__ void k_count(const unsigned* __restrict__ F) {
    int t = blockIdx.x * blockDim.x + threadIdx.x;
    if (t >= TOT) return;
    unsigned m = F[t]; if (INV) m = ~m;
    if (!m) return;
    int base = t * 32, b = t >> 13;
    while (m) {
        int j = __ffs(m) - 1;
        int e = runlen(m, j);
        int i = base + j;
        int r = findroot_h(i);
        g_L[i] = r;                      // owner-only write of final root
        atomicAdd(&g_sz[r], e);
        if (r == i) atomicAdd(&g_nc[b], 1);
        m &= ~runmask(j, e);
    }
}

// resolve root at a run start (immediate when compression held; chase as insurance)
__device__ __forceinline__ int root_at(int i) {
    int r = g_L[i];
    while (g_L[r] != r) r = g_L[r];
    return r;
}

__global__ void k_filter(unsigned* F, int min_size, int use_guard) {
    int t = blockIdx.x * blockDim.x + threadIdx.x;
    if (t >= TOT) return;
    unsigned m = F[t];
    if (!m) return;
    int b = t >> 13;
    if (use_guard && g_nc[b] <= 1) return;
    int base = t * 32;
    unsigned keep = m, mm = m;
    while (mm) {
        int j = __ffs(mm) - 1;
        int e = runlen(mm, j);
        if (g_sz[root_at(base + j)] < min_size) keep &= ~runmask(j, e);
        mm &= ~runmask(j, e);
    }
    if (keep != m) F[t] = keep;
}

__global__ void k_fill(unsigned* F, int thresh) {
    int t = blockIdx.x * blockDim.x + threadIdx.x;
    if (t >= TOT) return;
    unsigned m = ~F[t];                  // background bits
    if (!m) return;
    int base = t * 32;
    unsigned add = 0, mm = m;
    while (mm) {
        int j = __ffs(mm) - 1;
        int e = runlen(mm, j);
        if (g_sz[root_at(base + j)] < thresh) add |= runmask(j, e);
        mm &= ~runmask(j, e);
    }
    if (add) F[t] |= add;
}

// ---------------- morphology on bitpacked ----------------
__host__ __device__ constexpr int hwidth(int R, int dy) {
    int w = 0;
    while ((w + 1) * (w + 1) + dy * dy <= R * R) ++w;
    return w;
}

template<int R, bool ER>
__global__ void k_morph(const unsigned* __restrict__ in, unsigned* __restrict__ out) {
    int t = blockIdx.x * blockDim.x + threadIdx.x;
    if (t >= TOT) return;
    int w = t & 15, y = (t >> 4) & 511, b = t >> 13;
    const unsigned* img = in + b * WPI;
    const unsigned border = ER ? 0xffffffffu : 0u;
    unsigned acc = border;
#pragma unroll
    for (int dy = -R; dy <= R; dy++) {
        int yy = y + dy;
        unsigned c, l, r;
        if (yy < 0 || yy >= HH) { c = border; l = border; r = border; }
        else {
            c = img[yy * WPR + w];
            l = (w > 0)  ? img[yy * WPR + w - 1] : border;
            r = (w < 15) ? img[yy * WPR + w + 1] : border;
        }
        unsigned rowacc = c;
        const int wd = hwidth(R, dy);
#pragma unroll
        for (int s = 1; s <= wd; s++) {
            unsigned rs = __funnelshift_r(c, r, s);   // sample x+s
            unsigned ls = __funnelshift_l(l, c, s);   // sample x-s
            if (ER) rowacc &= rs & ls; else rowacc |= rs | ls;
        }
        if (ER) acc &= rowacc; else acc |= rowacc;
    }
    out[t] = acc;
}

// ---------------- final dilate(disk1) + unpack float ----------------
__global__ void k_out(const unsigned* __restrict__ in, float* __restrict__ out) {
    int g = blockIdx.x * blockDim.x + threadIdx.x;
    if (g >= NN) return;
    int lane = g & 31;
    int t = g >> 5;
    int w = t & 15, y = (t >> 4) & 511, b = t >> 13;
    const unsigned* img = in + b * WPI;
    unsigned c = img[y * WPR + w];
    unsigned l = (w > 0)   ? img[y * WPR + w - 1] : 0u;
    unsigned r = (w < 15)  ? img[y * WPR + w + 1] : 0u;
    unsigned u = (y > 0)   ? img[(y - 1) * WPR + w] : 0u;
    unsigned d = (y < 511) ? img[(y + 1) * WPR + w] : 0u;
    unsigned res = c | u | d | __funnelshift_r(c, r, 1) | __funnelshift_l(l, c, 1);
    out[b * HW + y * WW + w * 32 + lane] = (float)((res >> lane) & 1u);
}

// ---------------- launch ----------------
extern "C" void kernel_launch(void* const* d_in, const int* in_sizes, int n_in,
                              void* d_out, int out_size) {
    (void)in_sizes; (void)n_in; (void)out_size;
    const float* in = (const float*)d_in[0];
    float* out = (float*)d_out;

    unsigned *F, *G;
    cudaGetSymbolAddress((void**)&F, g_F);
    cudaGetSymbolAddress((void**)&G, g_G);

    const int TPB = 256;
    const int gw = (TOT + TPB - 1) / TPB;        // word-granular kernels
    const int gp = (NN + TPB - 1) / TPB;         // pixel-granular kernels

    // pack: fg = input > 0
    k_pack<<<gp, TPB>>>(in);

    // --- remove_small_objects(fg, 2000, guarded) ---
    k_cinit<false><<<gw, TPB>>>(F);
    k_merge<false><<<gw, TPB>>>(F);
    k_count<false><<<gw, TPB>>>(F);
    k_filter<<<gw, TPB>>>(F, 2000, 1);

    // --- fill small holes: bg components < 301 px ---
    k_cinit<true><<<gw, TPB>>>(F);
    k_merge<true><<<gw, TPB>>>(F);
    k_count<true><<<gw, TPB>>>(F);
    k_fill<<<gw, TPB>>>(F, 301);

    // --- erode disk(2), then opening disk(5) ---
    k_morph<2, true ><<<gw, TPB>>>(F, G);
    k_morph<5, true ><<<gw, TPB>>>(G, F);
    k_morph<5, false><<<gw, TPB>>>(F, G);

    // --- remove_small_objects(fg, 2000, guarded) on G ---
    k_cinit<false><<<gw, TPB>>>(G);
    k_merge<false><<<gw, TPB>>>(G);
    k_count<false><<<gw, TPB>>>(G);
    k_filter<<<gw, TPB>>>(G, 2000, 1);

    // --- dilate disk(1) -> float out ---
    k_out<<<gp, TPB>>>(G, out);
}